// round 13
// baseline (speedup 1.0000x reference)
#include <cuda_runtime.h>
#include <cuda_fp16.h>
#include <cstdint>

#define BB 2
#define LL 2048
#define TT 4096
#define DM 512
#define DIN 1024
#define NH 16
#define HD 64
#define DS 64
#define DCONV 1152
#define DPROJ 2192
#define EPSF 1e-5f
#define CH 16
#define NSPLIT 8

// ---------------- scratch ----------------
__device__ __half g_xnh[TT * DM];
__device__ float g_zx0[TT * DPROJ];
__device__ float g_zx1[TT * DPROJ];
__device__ float g_xbc0[TT * DCONV];
__device__ float g_xbc1[TT * DCONV];
__device__ float g_dt[2 * BB * NH * LL];
__device__ float g_dA[2 * BB * NH * LL];
__device__ float g_ysp[(size_t)(2 * NSPLIT) * TT * DIN];   // [dir*8+split][t][din]
__device__ __half g_ynh0[TT * DIN];
__device__ __half g_ynh1[TT * DIN];
__device__ __half g_finwh[DPROJ * DM];
__device__ __half g_binwh[DPROJ * DM];
__device__ __half g_pwh[DM * DIN];
__device__ __half g_fTh[DIN * DM];
__device__ __half g_bTh[DIN * DM];
__device__ __half g_wcath[DM * 2 * DIN];

// ---------------- prep: rmsnorm + weight converts + transposes (one launch) --------
#define PREP_RMS   4096
#define PREP_CVT1  2192
#define PREP_CVT2  2192
#define PREP_CVTP  1024
#define PREP_TR    512
#define PREP_BLKS  (PREP_RMS + PREP_CVT1 + PREP_CVT2 + PREP_CVTP + 2 * PREP_TR)

__global__ __launch_bounds__(256) void prep_kernel(
    const float* __restrict__ x, const float* __restrict__ nw, __half* __restrict__ xnh,
    const float* __restrict__ finw, __half* __restrict__ finwh,
    const float* __restrict__ binw, __half* __restrict__ binwh,
    const float* __restrict__ pw, __half* __restrict__ pwh,
    const float* __restrict__ fow, __half* __restrict__ fTh,
    const float* __restrict__ bow, __half* __restrict__ bTh) {
    int blk = blockIdx.x;
    int tid = threadIdx.x;
    if (blk < PREP_RMS) {
        int t = blk;
        float v[2];
        float ss = 0.f;
#pragma unroll
        for (int it = 0; it < 2; it++) {
            v[it] = x[(size_t)t * DM + tid + it * 256];
            ss += v[it] * v[it];
        }
#pragma unroll
        for (int o = 16; o > 0; o >>= 1) ss += __shfl_xor_sync(~0u, ss, o);
        __shared__ float ws[8];
        if ((tid & 31) == 0) ws[tid >> 5] = ss;
        __syncthreads();
        float tot = 0.f;
#pragma unroll
        for (int w = 0; w < 8; w++) tot += ws[w];
        float sc = rsqrtf(tot / (float)DM + EPSF);
#pragma unroll
        for (int it = 0; it < 2; it++) {
            int j = tid + it * 256;
            xnh[(size_t)t * DM + j] = __float2half(v[it] * sc * nw[j]);
        }
        return;
    }
    blk -= PREP_RMS;
    if (blk < PREP_CVT1 + PREP_CVT2 + PREP_CVTP) {
        const float* s;
        __half* d;
        int i;
        if (blk < PREP_CVT1) { s = finw; d = finwh; i = blk * 256 + tid; }
        else if (blk < PREP_CVT1 + PREP_CVT2) { s = binw; d = binwh; i = (blk - PREP_CVT1) * 256 + tid; }
        else { s = pw; d = pwh; i = (blk - PREP_CVT1 - PREP_CVT2) * 256 + tid; }
        float2 v = *(const float2*)(s + (size_t)i * 2);
        *(__half2*)(d + (size_t)i * 2) = __floats2half2_rn(v.x, v.y);
        return;
    }
    blk -= PREP_CVT1 + PREP_CVT2 + PREP_CVTP;
    {
        const float* S;
        __half* T;
        int b;
        if (blk < PREP_TR) { S = fow; T = fTh; b = blk; }
        else { S = bow; T = bTh; b = blk - PREP_TR; }
        int c0 = (b & 31) * 32, r0 = (b >> 5) * 32;
        int tx = tid & 31, ty = tid >> 5;
        __shared__ float tile[32][33];
#pragma unroll
        for (int i = ty; i < 32; i += 8)
            tile[i][tx] = S[(size_t)(r0 + i) * DIN + c0 + tx];
        __syncthreads();
#pragma unroll
        for (int i = ty; i < 32; i += 8)
            T[(size_t)(c0 + i) * DM + r0 + tx] = __float2half(tile[tx][i]);
    }
}

// ---------------- pipelined fp16 NT GEMM (mma.m16n8k16, fp32 accum) ----------------
template <int BM>
__global__ __launch_bounds__(256) void gemm_h(
    const __half* __restrict__ A, const __half* __restrict__ A2,
    const __half* W, void* Cv,
    const __half* Wb, void* Cvb,
    int N, int K, int lda, int ldc, int aoff, int mode, int outh,
    const float* __restrict__ bias, const float* __restrict__ resid) {
    constexpr int BN = 128;
    constexpr int STRH = 40;
    constexpr int STAGES = 3;
    constexpr int NT = (BM == 128) ? 8 : 4;
    constexpr int STAGEH = (BM + BN) * STRH;
    extern __shared__ __align__(16) char smraw[];
    __half* sM = (__half*)smraw;

    if (blockIdx.z) { W = Wb; Cv = Cvb; mode = 1; }

    int tid = threadIdx.x;
    int warp = tid >> 5, lane = tid & 31;
    int m0 = blockIdx.y * BM, n0 = blockIdx.x * BN;
    int tg = lane >> 2, tk = lane & 3;
    int wm, wn;
    if (BM == 128) { wm = (warp & 3) * 32; wn = (warp >> 2) * 64; }
    else           { wm = (warp & 1) * 32; wn = (warp >> 1) * 32; }

    float acc[2][NT][4];
#pragma unroll
    for (int mt = 0; mt < 2; mt++)
#pragma unroll
        for (int nt = 0; nt < NT; nt++)
#pragma unroll
            for (int r = 0; r < 4; r++) acc[mt][nt][r] = 0.f;

    int lrA = (BM == 128) ? (tid >> 1) : (tid >> 2);
    int kA0 = (BM == 128) ? ((tid & 1) * 16) : ((tid & 3) * 8);
    constexpr int NCHA = (BM == 128) ? 2 : 1;
    int gr = m0 + lrA;
    int bb = gr >> 11, sidx = gr & 2047;
    int frow = (bb << 11) + (2047 - sidx);
    const __half* arow0;
    const __half* arow1 = nullptr;
    if (mode == 2) {
        arow0 = A + (size_t)gr * lda;
        arow1 = A2 + (size_t)frow * lda - lda;
    } else {
        int row = (mode == 1) ? frow : gr;
        arow0 = A + (size_t)row * lda + aoff;
    }
    int lrB = tid >> 1;
    int kB0 = (tid & 1) * 16;
    int nr = n0 + lrB;
    const __half* wrow = W + (size_t)(nr < N ? nr : 0) * K;
    int wsz = (nr < N) ? 16 : 0;

    auto issue = [&](int chunk, int stg) {
        int k0 = chunk * 32;
        __half* dA = sM + stg * STAGEH + lrA * STRH;
#pragma unroll
        for (int c = 0; c < NCHA; c++) {
            int kb = k0 + kA0 + c * 8;
            const __half* src = (mode == 2 && kb >= lda) ? (arow1 + kb) : (arow0 + kb);
            unsigned d = (unsigned)__cvta_generic_to_shared(dA + kA0 + c * 8);
            asm volatile("cp.async.ca.shared.global [%0], [%1], 16;\n" ::"r"(d), "l"(src));
        }
        __half* dB = sM + stg * STAGEH + BM * STRH + lrB * STRH;
#pragma unroll
        for (int c = 0; c < 2; c++) {
            int kb = k0 + kB0 + c * 8;
            unsigned d = (unsigned)__cvta_generic_to_shared(dB + kB0 + c * 8);
            asm volatile("cp.async.ca.shared.global [%0], [%1], 16, %2;\n"
                         ::"r"(d), "l"(wrow + kb), "r"(wsz));
        }
        asm volatile("cp.async.commit_group;\n");
    };

    int NC = K / 32;
    issue(0, 0);
    issue(1, 1);

    for (int c = 0; c < NC; c++) {
        asm volatile("cp.async.wait_group 1;\n");
        __syncthreads();
        if (c + 2 < NC) issue(c + 2, (c + 2) % STAGES);
        const uint32_t* pA = (const uint32_t*)(sM + (c % STAGES) * STAGEH);
        const uint32_t* pB = pA + BM * (STRH / 2);
#pragma unroll
        for (int ks = 0; ks < 2; ks++) {
            int kb = ks * 8;
            uint32_t af[2][4], bf[NT][2];
#pragma unroll
            for (int mt = 0; mt < 2; mt++) {
                int mb = wm + mt * 16 + tg;
                af[mt][0] = pA[mb * 20 + kb + tk];
                af[mt][1] = pA[(mb + 8) * 20 + kb + tk];
                af[mt][2] = pA[mb * 20 + kb + tk + 4];
                af[mt][3] = pA[(mb + 8) * 20 + kb + tk + 4];
            }
#pragma unroll
            for (int nt = 0; nt < NT; nt++) {
                int nb = wn + nt * 8 + tg;
                bf[nt][0] = pB[nb * 20 + kb + tk];
                bf[nt][1] = pB[nb * 20 + kb + tk + 4];
            }
#pragma unroll
            for (int mt = 0; mt < 2; mt++)
#pragma unroll
                for (int nt = 0; nt < NT; nt++) {
                    asm volatile(
                        "mma.sync.aligned.m16n8k16.row.col.f32.f16.f16.f32 "
                        "{%0,%1,%2,%3}, {%4,%5,%6,%7}, {%8,%9}, {%0,%1,%2,%3};\n"
                        : "+f"(acc[mt][nt][0]), "+f"(acc[mt][nt][1]),
                          "+f"(acc[mt][nt][2]), "+f"(acc[mt][nt][3])
                        : "r"(af[mt][0]), "r"(af[mt][1]), "r"(af[mt][2]), "r"(af[mt][3]),
                          "r"(bf[nt][0]), "r"(bf[nt][1]));
                }
        }
        __syncthreads();
    }

#pragma unroll
    for (int mt = 0; mt < 2; mt++) {
        int r0 = m0 + wm + mt * 16 + tg;
#pragma unroll
        for (int nt = 0; nt < NT; nt++) {
            int c0 = n0 + wn + nt * 8 + 2 * tk;
            if (c0 >= N) continue;
#pragma unroll
            for (int half = 0; half < 2; half++) {
                int r = r0 + half * 8;
                float v0 = acc[mt][nt][half * 2 + 0];
                float v1 = acc[mt][nt][half * 2 + 1];
                if (bias) { v0 += bias[c0]; v1 += bias[c0 + 1]; }
                if (resid) {
                    v0 += resid[(size_t)r * ldc + c0];
                    v1 += resid[(size_t)r * ldc + c0 + 1];
                }
                if (outh) {
                    *(__half2*)((__half*)Cv + (size_t)r * ldc + c0) = __floats2half2_rn(v0, v1);
                } else {
                    float* C = (float*)Cv;
                    C[(size_t)r * ldc + c0] = v0;
                    C[(size_t)r * ldc + c0 + 1] = v1;
                }
            }
        }
    }
}

// ---------------- fused conv+silu and dt/dA ----------------
#define CONV_BLKS 36864
#define DT_BLKS   512

__global__ __launch_bounds__(256) void convdt_kernel(
    const float* __restrict__ zx0, const float* __restrict__ zx1,
    const float* __restrict__ cwf, const float* __restrict__ cbf,
    const float* __restrict__ cwb, const float* __restrict__ cbb,
    float* __restrict__ xbc0, float* __restrict__ xbc1,
    const float* __restrict__ dtbf, const float* __restrict__ Alf,
    const float* __restrict__ dtbb, const float* __restrict__ Alb,
    float* __restrict__ dtg, float* __restrict__ dAg) {
    int blk = blockIdx.x;
    int tid = threadIdx.x;
    if (blk < CONV_BLKS) {
        int idx = blk * 256 + tid;
        const int per = TT * DCONV;
        int d = idx / per;
        int r = idx - d * per;
        int t = r / DCONV;
        int c = r - t * DCONV;
        int b = t >> 11, s = t & 2047;
        const float* zx = d ? zx1 : zx0;
        const float* cw = d ? cwb : cwf;
        const float* cb = d ? cbb : cbf;
        float acc = cb[c];
#pragma unroll
        for (int i = 0; i < 4; i++) {
            int ss = s - 3 + i;
            if (ss >= 0)
                acc = fmaf(cw[c * 4 + i], zx[(size_t)((b << 11) + ss) * DPROJ + DIN + c], acc);
        }
        float v = acc / (1.f + expf(-acc));
        (d ? xbc1 : xbc0)[(size_t)t * DCONV + c] = v;
        return;
    }
    int idx = (blk - CONV_BLKS) * 256 + tid;
    int d = idx / (TT * NH);
    int r = idx - d * (TT * NH);
    int t = r / NH;
    int h = r - t * NH;
    int b = t >> 11, s = t & 2047;
    const float* zx = d ? zx1 : zx0;
    float raw = zx[(size_t)t * DPROJ + (DPROJ - NH) + h] + (d ? dtbb : dtbf)[h];
    float dtv = (raw > 20.f) ? raw : log1pf(expf(raw));
    float dAv = expf(-expf((d ? Alb : Alf)[h]) * dtv);
    int row = ((d * BB + b) * NH + h);
    dtg[(size_t)row * LL + s] = dtv;
    dAg[(size_t)row * LL + s] = dAv;
}

// ---------------- SSM scan, state-split 8x: 512 CTAs, 8 states each ----------------
// Thread: p = tid>>2 (headdim row), q = tid&3 -> 2 states. Batched shfl reduction.
__global__ __launch_bounds__(256) void scan8_kernel(
    const float* __restrict__ xbc0, const float* __restrict__ xbc1,
    const float* __restrict__ dtg, const float* __restrict__ dAg,
    const float* __restrict__ Df, const float* __restrict__ Db,
    float* __restrict__ ysp) {
    int bid = blockIdx.x;          // 512
    int sp = bid & 7;
    int sid = bid >> 3;
    int d = sid >> 5;
    int b = (sid >> 4) & 1;
    int hh = sid & 15;
    const float* xbc = d ? xbc1 : xbc0;
    float Dh = (d ? Db : Df)[hh];
    float* yout = ysp + (size_t)(d * NSPLIT + sp) * TT * DIN;
    int tid = threadIdx.x;
    int p = tid >> 2, q = tid & 3;
    int scrow = ((d * BB + b) * NH + hh) * LL;
    float Dcoef = (sp == 0 && q == 0) ? Dh : 0.f;

    __shared__ float4 sxs[2][CH][16];   // xs: 64 floats/step
    __shared__ float4 sbc[2][CH][4];    // B(8) + C(8) this split, per step
    __shared__ float4 sdA[2][4];
    __shared__ float4 sdt[2][4];

    auto issue_chunk = [&](int c, int buf) {
        int s0 = c * CH;
        for (int ii = tid; ii < 328; ii += 256) {
            const float* src;
            void* dst;
            if (ii < 256) {
                int j = ii >> 4, w = ii & 15;
                src = xbc + (size_t)((b << 11) + s0 + j) * DCONV + hh * 64 + w * 4;
                dst = &sxs[buf][j][w];
            } else if (ii < 320) {
                int r = ii - 256;
                int j = r >> 2, w = r & 3;
                int col = (w < 2) ? (1024 + sp * 8 + w * 4) : (1088 + sp * 8 + (w - 2) * 4);
                src = xbc + (size_t)((b << 11) + s0 + j) * DCONV + col;
                dst = &sbc[buf][j][w];
            } else {
                int k2 = ii - 320;
                if (k2 < 4) { src = dAg + (size_t)scrow + s0 + k2 * 4; dst = &sdA[buf][k2]; }
                else        { src = dtg + (size_t)scrow + s0 + (k2 - 4) * 4; dst = &sdt[buf][k2 - 4]; }
            }
            unsigned sm = (unsigned)__cvta_generic_to_shared(dst);
            asm volatile("cp.async.ca.shared.global [%0], [%1], 16;\n" ::"r"(sm), "l"(src));
        }
        asm volatile("cp.async.commit_group;\n");
    };

    float h0 = 0.f, h1 = 0.f;

    issue_chunk(0, 0);
    issue_chunk(1, 1);

    const int NCHUNK = LL / CH;
    for (int c = 0; c < NCHUNK; c++) {
        int buf = c & 1;
        asm volatile("cp.async.wait_group 1;\n");
        __syncthreads();
        int s0 = c * CH;
        const float* dAp = (const float*)sdA[buf];
        const float* dtp = (const float*)sdt[buf];
        float yreg[CH];
#pragma unroll
        for (int j = 0; j < CH; j++) {
            float dAv = dAp[j];
            float dtv = dtp[j];
            float xsv = ((const float*)sxs[buf][j])[p];
            float dtx = dtv * xsv;
            float2 Bv = ((const float2*)&sbc[buf][j][0])[q];
            float2 Cv = ((const float2*)&sbc[buf][j][2])[q];
            h0 = fmaf(dAv, h0, dtx * Bv.x);
            h1 = fmaf(dAv, h1, dtx * Bv.y);
            yreg[j] = fmaf(h0, Cv.x, fmaf(h1, Cv.y, Dcoef * xsv));
        }
#pragma unroll
        for (int j = 0; j < CH; j++) {
            float v = yreg[j];
            v += __shfl_xor_sync(~0u, v, 1);
            v += __shfl_xor_sync(~0u, v, 2);
            yreg[j] = v;
        }
        if (q == 0) {
#pragma unroll
            for (int j = 0; j < CH; j++)
                yout[(size_t)((b << 11) + s0 + j) * DIN + hh * 64 + p] = yreg[j];
        }
        __syncthreads();
        if (c + 2 < NCHUNK) issue_chunk(c + 2, buf);
        else asm volatile("cp.async.commit_group;\n");
    }
}

// ---------------- gating + inner rmsnorm (sums 8 split partials) -> fp16 -------------
__global__ __launch_bounds__(256) void gate_norm_kernel(
    const float* __restrict__ ysp,
    const float* __restrict__ zx0, const float* __restrict__ zx1,
    const float* __restrict__ nwf, const float* __restrict__ nwb,
    __half* __restrict__ yn0, __half* __restrict__ yn1) {
    int blk = blockIdx.x;
    int d = blk >> 12;
    int t = blk & 4095;
    const float* pp[NSPLIT];
#pragma unroll
    for (int s = 0; s < NSPLIT; s++)
        pp[s] = ysp + (size_t)(d * NSPLIT + s) * TT * DIN;
    const float* zx = d ? zx1 : zx0;
    const float* nw = d ? nwb : nwf;
    __half* yn = d ? yn1 : yn0;
    int tid = threadIdx.x;
    float g[4];
    float ss = 0.f;
#pragma unroll
    for (int it = 0; it < 4; it++) {
        int j = tid + it * 256;
        size_t o = (size_t)t * DIN + j;
        float y = ((pp[0][o] + pp[1][o]) + (pp[2][o] + pp[3][o])) +
                  ((pp[4][o] + pp[5][o]) + (pp[6][o] + pp[7][o]));
        float z = zx[(size_t)t * DPROJ + j];
        float gz = z / (1.f + expf(-z));
        float v = y * gz;
        g[it] = v;
        ss += v * v;
    }
#pragma unroll
    for (int o = 16; o > 0; o >>= 1) ss += __shfl_xor_sync(~0u, ss, o);
    __shared__ float ws[8];
    if ((tid & 31) == 0) ws[tid >> 5] = ss;
    __syncthreads();
    float tot = 0.f;
#pragma unroll
    for (int w = 0; w < 8; w++) tot += ws[w];
    float sc = rsqrtf(tot / (float)DIN + EPSF);
#pragma unroll
    for (int it = 0; it < 4; it++) {
        int j = tid + it * 256;
        yn[(size_t)t * DIN + j] = __float2half(g[it] * sc * nw[j]);
    }
}

// ---------------- host launch ----------------
extern "C" void kernel_launch(void* const* d_in, const int* in_sizes, int n_in,
                              void* d_out, int out_size) {
    bool sig = (in_sizes[2] == DPROJ * DM);
    const float* x = (const float*)d_in[0];
    const float* nw = (const float*)d_in[1];
    int bf = sig ? 2 : 4;
    int bw = sig ? 10 : 12;
    const float* f_in_w = (const float*)d_in[bf + 0];
    const float* f_cw   = (const float*)d_in[bf + 1];
    const float* f_cb   = (const float*)d_in[bf + 2];
    const float* f_dtb  = (const float*)d_in[bf + 3];
    const float* f_Al   = (const float*)d_in[bf + 4];
    const float* f_D    = (const float*)d_in[bf + 5];
    const float* f_nw   = (const float*)d_in[bf + 6];
    const float* f_ow   = (const float*)d_in[bf + 7];
    const float* b_in_w = (const float*)d_in[bw + 0];
    const float* b_cw   = (const float*)d_in[bw + 1];
    const float* b_cb   = (const float*)d_in[bw + 2];
    const float* b_dtb  = (const float*)d_in[bw + 3];
    const float* b_Al   = (const float*)d_in[bw + 4];
    const float* b_D    = (const float*)d_in[bw + 5];
    const float* b_nw   = (const float*)d_in[bw + 6];
    const float* b_ow   = (const float*)d_in[bw + 7];
    const float* pw = (const float*)d_in[sig ? 18 : 2];
    const float* pb = (const float*)d_in[sig ? 19 : 3];

    __half *xnh, *ynh0, *ynh1, *finwh, *binwh, *pwh, *fTh, *bTh, *wcath;
    float *zx0, *zx1, *xbc0, *xbc1, *dtg, *dAg, *ysp;
    cudaGetSymbolAddress((void**)&xnh, g_xnh);
    cudaGetSymbolAddress((void**)&zx0, g_zx0);
    cudaGetSymbolAddress((void**)&zx1, g_zx1);
    cudaGetSymbolAddress((void**)&xbc0, g_xbc0);
    cudaGetSymbolAddress((void**)&xbc1, g_xbc1);
    cudaGetSymbolAddress((void**)&dtg, g_dt);
    cudaGetSymbolAddress((void**)&dAg, g_dA);
    cudaGetSymbolAddress((void**)&ysp, g_ysp);
    cudaGetSymbolAddress((void**)&ynh0, g_ynh0);
    cudaGetSymbolAddress((void**)&ynh1, g_ynh1);
    cudaGetSymbolAddress((void**)&finwh, g_finwh);
    cudaGetSymbolAddress((void**)&binwh, g_binwh);
    cudaGetSymbolAddress((void**)&pwh, g_pwh);
    cudaGetSymbolAddress((void**)&fTh, g_fTh);
    cudaGetSymbolAddress((void**)&bTh, g_bTh);
    cudaGetSymbolAddress((void**)&wcath, g_wcath);

    const int SM128 = 3 * (128 + 128) * 40 * 2;
    const int SM64  = 3 * (64 + 128) * 40 * 2;
    cudaFuncSetAttribute(gemm_h<128>, cudaFuncAttributeMaxDynamicSharedMemorySize, SM128);
    cudaFuncSetAttribute(gemm_h<64>,  cudaFuncAttributeMaxDynamicSharedMemorySize, SM64);

    // 1: prep
    prep_kernel<<<PREP_BLKS, 256>>>(x, nw, xnh, f_in_w, finwh, b_in_w, binwh,
                                    pw, pwh, f_ow, fTh, b_ow, bTh);

    // 2: both in-projections
    gemm_h<128><<<dim3((DPROJ + 127) / 128, TT / 128, 2), 256, SM128>>>(
        xnh, nullptr, finwh, zx0, binwh, zx1, DPROJ, DM, DM, DPROJ, 0, 0, 0, nullptr, nullptr);

    // 3: fused conv + dt
    convdt_kernel<<<CONV_BLKS + DT_BLKS, 256>>>(zx0, zx1, f_cw, f_cb, b_cw, b_cb,
                                                xbc0, xbc1, f_dtb, f_Al, b_dtb, b_Al, dtg, dAg);

    // 4: scan (PROFILED SLOT) — 512 CTAs, split-8
    scan8_kernel<<<512, 256>>>(xbc0, xbc1, dtg, dAg, f_D, b_D, ysp);

    // 5-6: tail weight combos
    gemm_h<128><<<dim3(DIN / 128, DM / 128), 256, SM128>>>(
        pwh, nullptr, fTh, wcath, nullptr, nullptr, DIN, DM, DIN, 2 * DIN, 0, 0, 1, nullptr, nullptr);
    gemm_h<128><<<dim3(DIN / 128, DM / 128), 256, SM128>>>(
        pwh, nullptr, bTh, wcath + DIN, nullptr, nullptr, DIN, DM, DIN, 2 * DIN, DM, 0, 1, nullptr, nullptr);

    // 7: gating + inner rmsnorm
    gate_norm_kernel<<<2 * TT, 256>>>(ysp, zx0, zx1, f_nw, b_nw, ynh0, ynh1);

    // 8: fused tail GEMM
    gemm_h<64><<<dim3(DM / 128, TT / 64), 256, SM64>>>(
        ynh0, ynh1, wcath, d_out, nullptr, nullptr, DM, 2 * DIN, DIN, DM, 0, 2, 0, pb, x);
}

// round 14
// speedup vs baseline: 1.3192x; 1.3192x over previous
#include <cuda_runtime.h>
#include <cuda_fp16.h>
#include <cstdint>

#define BB 2
#define LL 2048
#define TT 4096
#define DM 512
#define DIN 1024
#define NH 16
#define HD 64
#define DS 64
#define DCONV 1152
#define DPROJ 2192
#define EPSF 1e-5f
#define CH 16
#define NSPLIT 4

// ---------------- scratch ----------------
__device__ __half g_xnh[TT * DM];
__device__ float g_zx0[TT * DPROJ];
__device__ float g_zx1[TT * DPROJ];
__device__ __half g_xbc0h[(size_t)TT * DCONV];
__device__ __half g_xbc1h[(size_t)TT * DCONV];
__device__ float g_dt[2 * BB * NH * LL];
__device__ float g_dA[2 * BB * NH * LL];
__device__ float g_ysp[(size_t)(2 * NSPLIT) * TT * DIN];   // [dir*4+split][t][din]
__device__ __half g_ynh0[TT * DIN];
__device__ __half g_ynh1[TT * DIN];
__device__ __half g_finwh[DPROJ * DM];
__device__ __half g_binwh[DPROJ * DM];
__device__ __half g_pwh[DM * DIN];
__device__ __half g_fTh[DIN * DM];
__device__ __half g_bTh[DIN * DM];
__device__ __half g_wcath[DM * 2 * DIN];

// ---------------- prep: rmsnorm + weight converts + transposes (one launch) --------
#define PREP_RMS   4096
#define PREP_CVT1  2192
#define PREP_CVT2  2192
#define PREP_CVTP  1024
#define PREP_TR    512
#define PREP_BLKS  (PREP_RMS + PREP_CVT1 + PREP_CVT2 + PREP_CVTP + 2 * PREP_TR)

__global__ __launch_bounds__(256) void prep_kernel(
    const float* __restrict__ x, const float* __restrict__ nw, __half* __restrict__ xnh,
    const float* __restrict__ finw, __half* __restrict__ finwh,
    const float* __restrict__ binw, __half* __restrict__ binwh,
    const float* __restrict__ pw, __half* __restrict__ pwh,
    const float* __restrict__ fow, __half* __restrict__ fTh,
    const float* __restrict__ bow, __half* __restrict__ bTh) {
    int blk = blockIdx.x;
    int tid = threadIdx.x;
    if (blk < PREP_RMS) {
        int t = blk;
        float v[2];
        float ss = 0.f;
#pragma unroll
        for (int it = 0; it < 2; it++) {
            v[it] = x[(size_t)t * DM + tid + it * 256];
            ss += v[it] * v[it];
        }
#pragma unroll
        for (int o = 16; o > 0; o >>= 1) ss += __shfl_xor_sync(~0u, ss, o);
        __shared__ float ws[8];
        if ((tid & 31) == 0) ws[tid >> 5] = ss;
        __syncthreads();
        float tot = 0.f;
#pragma unroll
        for (int w = 0; w < 8; w++) tot += ws[w];
        float sc = rsqrtf(tot / (float)DM + EPSF);
#pragma unroll
        for (int it = 0; it < 2; it++) {
            int j = tid + it * 256;
            xnh[(size_t)t * DM + j] = __float2half(v[it] * sc * nw[j]);
        }
        return;
    }
    blk -= PREP_RMS;
    if (blk < PREP_CVT1 + PREP_CVT2 + PREP_CVTP) {
        const float* s;
        __half* d;
        int i;
        if (blk < PREP_CVT1) { s = finw; d = finwh; i = blk * 256 + tid; }
        else if (blk < PREP_CVT1 + PREP_CVT2) { s = binw; d = binwh; i = (blk - PREP_CVT1) * 256 + tid; }
        else { s = pw; d = pwh; i = (blk - PREP_CVT1 - PREP_CVT2) * 256 + tid; }
        float2 v = *(const float2*)(s + (size_t)i * 2);
        *(__half2*)(d + (size_t)i * 2) = __floats2half2_rn(v.x, v.y);
        return;
    }
    blk -= PREP_CVT1 + PREP_CVT2 + PREP_CVTP;
    {
        const float* S;
        __half* T;
        int b;
        if (blk < PREP_TR) { S = fow; T = fTh; b = blk; }
        else { S = bow; T = bTh; b = blk - PREP_TR; }
        int c0 = (b & 31) * 32, r0 = (b >> 5) * 32;
        int tx = tid & 31, ty = tid >> 5;
        __shared__ float tile[32][33];
#pragma unroll
        for (int i = ty; i < 32; i += 8)
            tile[i][tx] = S[(size_t)(r0 + i) * DIN + c0 + tx];
        __syncthreads();
#pragma unroll
        for (int i = ty; i < 32; i += 8)
            T[(size_t)(c0 + i) * DM + r0 + tx] = __float2half(tile[tx][i]);
    }
}

// ---------------- pipelined fp16 NT GEMM (mma.m16n8k16, fp32 accum) ----------------
template <int BM>
__global__ __launch_bounds__(256) void gemm_h(
    const __half* __restrict__ A, const __half* __restrict__ A2,
    const __half* W, void* Cv,
    const __half* Wb, void* Cvb,
    int N, int K, int lda, int ldc, int aoff, int mode, int outh,
    const float* __restrict__ bias, const float* __restrict__ resid) {
    constexpr int BN = 128;
    constexpr int STRH = 40;
    constexpr int STAGES = 3;
    constexpr int NT = (BM == 128) ? 8 : 4;
    constexpr int STAGEH = (BM + BN) * STRH;
    extern __shared__ __align__(16) char smraw[];
    __half* sM = (__half*)smraw;

    if (blockIdx.z) { W = Wb; Cv = Cvb; mode = 1; }

    int tid = threadIdx.x;
    int warp = tid >> 5, lane = tid & 31;
    int m0 = blockIdx.y * BM, n0 = blockIdx.x * BN;
    int tg = lane >> 2, tk = lane & 3;
    int wm, wn;
    if (BM == 128) { wm = (warp & 3) * 32; wn = (warp >> 2) * 64; }
    else           { wm = (warp & 1) * 32; wn = (warp >> 1) * 32; }

    float acc[2][NT][4];
#pragma unroll
    for (int mt = 0; mt < 2; mt++)
#pragma unroll
        for (int nt = 0; nt < NT; nt++)
#pragma unroll
            for (int r = 0; r < 4; r++) acc[mt][nt][r] = 0.f;

    int lrA = (BM == 128) ? (tid >> 1) : (tid >> 2);
    int kA0 = (BM == 128) ? ((tid & 1) * 16) : ((tid & 3) * 8);
    constexpr int NCHA = (BM == 128) ? 2 : 1;
    int gr = m0 + lrA;
    int bb = gr >> 11, sidx = gr & 2047;
    int frow = (bb << 11) + (2047 - sidx);
    const __half* arow0;
    const __half* arow1 = nullptr;
    if (mode == 2) {
        arow0 = A + (size_t)gr * lda;
        arow1 = A2 + (size_t)frow * lda - lda;
    } else {
        int row = (mode == 1) ? frow : gr;
        arow0 = A + (size_t)row * lda + aoff;
    }
    int lrB = tid >> 1;
    int kB0 = (tid & 1) * 16;
    int nr = n0 + lrB;
    const __half* wrow = W + (size_t)(nr < N ? nr : 0) * K;
    int wsz = (nr < N) ? 16 : 0;

    auto issue = [&](int chunk, int stg) {
        int k0 = chunk * 32;
        __half* dA = sM + stg * STAGEH + lrA * STRH;
#pragma unroll
        for (int c = 0; c < NCHA; c++) {
            int kb = k0 + kA0 + c * 8;
            const __half* src = (mode == 2 && kb >= lda) ? (arow1 + kb) : (arow0 + kb);
            unsigned d = (unsigned)__cvta_generic_to_shared(dA + kA0 + c * 8);
            asm volatile("cp.async.ca.shared.global [%0], [%1], 16;\n" ::"r"(d), "l"(src));
        }
        __half* dB = sM + stg * STAGEH + BM * STRH + lrB * STRH;
#pragma unroll
        for (int c = 0; c < 2; c++) {
            int kb = k0 + kB0 + c * 8;
            unsigned d = (unsigned)__cvta_generic_to_shared(dB + kB0 + c * 8);
            asm volatile("cp.async.ca.shared.global [%0], [%1], 16, %2;\n"
                         ::"r"(d), "l"(wrow + kb), "r"(wsz));
        }
        asm volatile("cp.async.commit_group;\n");
    };

    int NC = K / 32;
    issue(0, 0);
    issue(1, 1);

    for (int c = 0; c < NC; c++) {
        asm volatile("cp.async.wait_group 1;\n");
        __syncthreads();
        if (c + 2 < NC) issue(c + 2, (c + 2) % STAGES);
        const uint32_t* pA = (const uint32_t*)(sM + (c % STAGES) * STAGEH);
        const uint32_t* pB = pA + BM * (STRH / 2);
#pragma unroll
        for (int ks = 0; ks < 2; ks++) {
            int kb = ks * 8;
            uint32_t af[2][4], bf[NT][2];
#pragma unroll
            for (int mt = 0; mt < 2; mt++) {
                int mb = wm + mt * 16 + tg;
                af[mt][0] = pA[mb * 20 + kb + tk];
                af[mt][1] = pA[(mb + 8) * 20 + kb + tk];
                af[mt][2] = pA[mb * 20 + kb + tk + 4];
                af[mt][3] = pA[(mb + 8) * 20 + kb + tk + 4];
            }
#pragma unroll
            for (int nt = 0; nt < NT; nt++) {
                int nb = wn + nt * 8 + tg;
                bf[nt][0] = pB[nb * 20 + kb + tk];
                bf[nt][1] = pB[nb * 20 + kb + tk + 4];
            }
#pragma unroll
            for (int mt = 0; mt < 2; mt++)
#pragma unroll
                for (int nt = 0; nt < NT; nt++) {
                    asm volatile(
                        "mma.sync.aligned.m16n8k16.row.col.f32.f16.f16.f32 "
                        "{%0,%1,%2,%3}, {%4,%5,%6,%7}, {%8,%9}, {%0,%1,%2,%3};\n"
                        : "+f"(acc[mt][nt][0]), "+f"(acc[mt][nt][1]),
                          "+f"(acc[mt][nt][2]), "+f"(acc[mt][nt][3])
                        : "r"(af[mt][0]), "r"(af[mt][1]), "r"(af[mt][2]), "r"(af[mt][3]),
                          "r"(bf[nt][0]), "r"(bf[nt][1]));
                }
        }
        __syncthreads();
    }

#pragma unroll
    for (int mt = 0; mt < 2; mt++) {
        int r0 = m0 + wm + mt * 16 + tg;
#pragma unroll
        for (int nt = 0; nt < NT; nt++) {
            int c0 = n0 + wn + nt * 8 + 2 * tk;
            if (c0 >= N) continue;
#pragma unroll
            for (int half = 0; half < 2; half++) {
                int r = r0 + half * 8;
                float v0 = acc[mt][nt][half * 2 + 0];
                float v1 = acc[mt][nt][half * 2 + 1];
                if (bias) { v0 += bias[c0]; v1 += bias[c0 + 1]; }
                if (resid) {
                    v0 += resid[(size_t)r * ldc + c0];
                    v1 += resid[(size_t)r * ldc + c0 + 1];
                }
                if (outh) {
                    *(__half2*)((__half*)Cv + (size_t)r * ldc + c0) = __floats2half2_rn(v0, v1);
                } else {
                    float* C = (float*)Cv;
                    C[(size_t)r * ldc + c0] = v0;
                    C[(size_t)r * ldc + c0 + 1] = v1;
                }
            }
        }
    }
}

// ---------------- fused conv+silu (fp16 out) and dt/dA ----------------
#define CONV_BLKS 36864
#define DT_BLKS   512

__global__ __launch_bounds__(256) void convdt_kernel(
    const float* __restrict__ zx0, const float* __restrict__ zx1,
    const float* __restrict__ cwf, const float* __restrict__ cbf,
    const float* __restrict__ cwb, const float* __restrict__ cbb,
    __half* __restrict__ xbc0h, __half* __restrict__ xbc1h,
    const float* __restrict__ dtbf, const float* __restrict__ Alf,
    const float* __restrict__ dtbb, const float* __restrict__ Alb,
    float* __restrict__ dtg, float* __restrict__ dAg) {
    int blk = blockIdx.x;
    int tid = threadIdx.x;
    if (blk < CONV_BLKS) {
        int idx = blk * 256 + tid;
        const int per = TT * DCONV;
        int d = idx / per;
        int r = idx - d * per;
        int t = r / DCONV;
        int c = r - t * DCONV;
        int b = t >> 11, s = t & 2047;
        const float* zx = d ? zx1 : zx0;
        const float* cw = d ? cwb : cwf;
        const float* cb = d ? cbb : cbf;
        float acc = cb[c];
#pragma unroll
        for (int i = 0; i < 4; i++) {
            int ss = s - 3 + i;
            if (ss >= 0)
                acc = fmaf(cw[c * 4 + i], zx[(size_t)((b << 11) + ss) * DPROJ + DIN + c], acc);
        }
        float v = acc / (1.f + expf(-acc));
        (d ? xbc1h : xbc0h)[(size_t)t * DCONV + c] = __float2half(v);
        return;
    }
    int idx = (blk - CONV_BLKS) * 256 + tid;
    int d = idx / (TT * NH);
    int r = idx - d * (TT * NH);
    int t = r / NH;
    int h = r - t * NH;
    int b = t >> 11, s = t & 2047;
    const float* zx = d ? zx1 : zx0;
    float raw = zx[(size_t)t * DPROJ + (DPROJ - NH) + h] + (d ? dtbb : dtbf)[h];
    float dtv = (raw > 20.f) ? raw : log1pf(expf(raw));
    float dAv = expf(-expf((d ? Alb : Alf)[h]) * dtv);
    int row = ((d * BB + b) * NH + h);
    dtg[(size_t)row * LL + s] = dtv;
    dAg[(size_t)row * LL + s] = dAv;
}

// ---------------- SSM scan, state-split 4x, fp16 inputs, batched reduction ----------
// 256 CTAs. cp.async per chunk: xs 128 + BC 64 + 8 = 200 16B-txns (vs 392 fp32).
__global__ __launch_bounds__(256) void scan4h_kernel(
    const __half* __restrict__ xbc0h, const __half* __restrict__ xbc1h,
    const float* __restrict__ dtg, const float* __restrict__ dAg,
    const float* __restrict__ Df, const float* __restrict__ Db,
    float* __restrict__ ysp) {
    int bid = blockIdx.x;          // 256
    int sp = bid & 3;
    int sid = bid >> 2;
    int d = sid >> 5;
    int b = (sid >> 4) & 1;
    int hh = sid & 15;
    const __half* xbc = d ? xbc1h : xbc0h;
    float Dh = (d ? Db : Df)[hh];
    float* yout = ysp + (size_t)(d * NSPLIT + sp) * TT * DIN;
    int tid = threadIdx.x;
    int p = tid >> 2, q = tid & 3;
    int scrow = ((d * BB + b) * NH + hh) * LL;
    float Dcoef = (sp == 0 && q == 0) ? Dh : 0.f;

    __shared__ __align__(16) __half sxs[2][CH][64];   // xs: 64 halves/step (128B)
    __shared__ __align__(16) __half sbc[2][CH][32];   // B(16)+C(16) halves this split
    __shared__ float4 sdA[2][4];
    __shared__ float4 sdt[2][4];

    auto issue_chunk = [&](int c, int buf) {
        int s0 = c * CH;
        // 200 txns total, 256 threads: at most one each
        int ii = tid;
        if (ii < 128) {
            int j = ii >> 3, w = ii & 7;
            const __half* src = xbc + (size_t)((b << 11) + s0 + j) * DCONV + hh * 64 + w * 8;
            unsigned sm = (unsigned)__cvta_generic_to_shared(&sxs[buf][j][w * 8]);
            asm volatile("cp.async.ca.shared.global [%0], [%1], 16;\n" ::"r"(sm), "l"(src));
        } else if (ii < 192) {
            int r = ii - 128;
            int j = r >> 2, w = r & 3;
            int col = (w < 2) ? (1024 + sp * 16 + w * 8) : (1088 + sp * 16 + (w - 2) * 8);
            const __half* src = xbc + (size_t)((b << 11) + s0 + j) * DCONV + col;
            unsigned sm = (unsigned)__cvta_generic_to_shared(&sbc[buf][j][w * 8]);
            asm volatile("cp.async.ca.shared.global [%0], [%1], 16;\n" ::"r"(sm), "l"(src));
        } else if (ii < 200) {
            int k2 = ii - 192;
            const float* src;
            void* dst;
            if (k2 < 4) { src = dAg + (size_t)scrow + s0 + k2 * 4; dst = &sdA[buf][k2]; }
            else        { src = dtg + (size_t)scrow + s0 + (k2 - 4) * 4; dst = &sdt[buf][k2 - 4]; }
            unsigned sm = (unsigned)__cvta_generic_to_shared(dst);
            asm volatile("cp.async.ca.shared.global [%0], [%1], 16;\n" ::"r"(sm), "l"(src));
        }
        asm volatile("cp.async.commit_group;\n");
    };

    float h[4];
#pragma unroll
    for (int i = 0; i < 4; i++) h[i] = 0.f;

    issue_chunk(0, 0);
    issue_chunk(1, 1);

    const int NCHUNK = LL / CH;
    for (int c = 0; c < NCHUNK; c++) {
        int buf = c & 1;
        asm volatile("cp.async.wait_group 1;\n");
        __syncthreads();
        int s0 = c * CH;
        const float* dAp = (const float*)sdA[buf];
        const float* dtp = (const float*)sdt[buf];
        float yreg[CH];
#pragma unroll
        for (int j = 0; j < CH; j++) {
            float dAv = dAp[j];
            float dtv = dtp[j];
            float xsv = __half2float(sxs[buf][j][p]);
            float dtx = dtv * xsv;
            const __half2* sb = (const __half2*)&sbc[buf][j][q * 4];
            const __half2* sc2 = (const __half2*)&sbc[buf][j][16 + q * 4];
            float2 B01 = __half22float2(sb[0]);
            float2 B23 = __half22float2(sb[1]);
            float2 C01 = __half22float2(sc2[0]);
            float2 C23 = __half22float2(sc2[1]);
            float a0, a1;
            h[0] = fmaf(dAv, h[0], dtx * B01.x); a0 = h[0] * C01.x;
            h[1] = fmaf(dAv, h[1], dtx * B01.y); a1 = h[1] * C01.y;
            h[2] = fmaf(dAv, h[2], dtx * B23.x); a0 = fmaf(h[2], C23.x, a0);
            h[3] = fmaf(dAv, h[3], dtx * B23.y); a1 = fmaf(h[3], C23.y, a1);
            yreg[j] = a0 + a1 + Dcoef * xsv;
        }
#pragma unroll
        for (int j = 0; j < CH; j++) {
            float v = yreg[j];
            v += __shfl_xor_sync(~0u, v, 1);
            v += __shfl_xor_sync(~0u, v, 2);
            yreg[j] = v;
        }
        if (q == 0) {
#pragma unroll
            for (int j = 0; j < CH; j++)
                yout[(size_t)((b << 11) + s0 + j) * DIN + hh * 64 + p] = yreg[j];
        }
        __syncthreads();
        if (c + 2 < NCHUNK) issue_chunk(c + 2, buf);
        else asm volatile("cp.async.commit_group;\n");
    }
}

// ---------------- gating + inner rmsnorm (sums 4 split partials) -> fp16 -------------
__global__ __launch_bounds__(256) void gate_norm_kernel(
    const float* __restrict__ ysp,
    const float* __restrict__ zx0, const float* __restrict__ zx1,
    const float* __restrict__ nwf, const float* __restrict__ nwb,
    __half* __restrict__ yn0, __half* __restrict__ yn1) {
    int blk = blockIdx.x;
    int d = blk >> 12;
    int t = blk & 4095;
    const float* p0 = ysp + (size_t)(d * NSPLIT + 0) * TT * DIN;
    const float* p1 = ysp + (size_t)(d * NSPLIT + 1) * TT * DIN;
    const float* p2 = ysp + (size_t)(d * NSPLIT + 2) * TT * DIN;
    const float* p3 = ysp + (size_t)(d * NSPLIT + 3) * TT * DIN;
    const float* zx = d ? zx1 : zx0;
    const float* nw = d ? nwb : nwf;
    __half* yn = d ? yn1 : yn0;
    int tid = threadIdx.x;
    float g[4];
    float ss = 0.f;
#pragma unroll
    for (int it = 0; it < 4; it++) {
        int j = tid + it * 256;
        size_t o = (size_t)t * DIN + j;
        float y = (p0[o] + p1[o]) + (p2[o] + p3[o]);
        float z = zx[(size_t)t * DPROJ + j];
        float gz = z / (1.f + expf(-z));
        float v = y * gz;
        g[it] = v;
        ss += v * v;
    }
#pragma unroll
    for (int o = 16; o > 0; o >>= 1) ss += __shfl_xor_sync(~0u, ss, o);
    __shared__ float ws[8];
    if ((tid & 31) == 0) ws[tid >> 5] = ss;
    __syncthreads();
    float tot = 0.f;
#pragma unroll
    for (int w = 0; w < 8; w++) tot += ws[w];
    float sc = rsqrtf(tot / (float)DIN + EPSF);
#pragma unroll
    for (int it = 0; it < 4; it++) {
        int j = tid + it * 256;
        yn[(size_t)t * DIN + j] = __float2half(g[it] * sc * nw[j]);
    }
}

// ---------------- host launch ----------------
extern "C" void kernel_launch(void* const* d_in, const int* in_sizes, int n_in,
                              void* d_out, int out_size) {
    bool sig = (in_sizes[2] == DPROJ * DM);
    const float* x = (const float*)d_in[0];
    const float* nw = (const float*)d_in[1];
    int bf = sig ? 2 : 4;
    int bw = sig ? 10 : 12;
    const float* f_in_w = (const float*)d_in[bf + 0];
    const float* f_cw   = (const float*)d_in[bf + 1];
    const float* f_cb   = (const float*)d_in[bf + 2];
    const float* f_dtb  = (const float*)d_in[bf + 3];
    const float* f_Al   = (const float*)d_in[bf + 4];
    const float* f_D    = (const float*)d_in[bf + 5];
    const float* f_nw   = (const float*)d_in[bf + 6];
    const float* f_ow   = (const float*)d_in[bf + 7];
    const float* b_in_w = (const float*)d_in[bw + 0];
    const float* b_cw   = (const float*)d_in[bw + 1];
    const float* b_cb   = (const float*)d_in[bw + 2];
    const float* b_dtb  = (const float*)d_in[bw + 3];
    const float* b_Al   = (const float*)d_in[bw + 4];
    const float* b_D    = (const float*)d_in[bw + 5];
    const float* b_nw   = (const float*)d_in[bw + 6];
    const float* b_ow   = (const float*)d_in[bw + 7];
    const float* pw = (const float*)d_in[sig ? 18 : 2];
    const float* pb = (const float*)d_in[sig ? 19 : 3];

    __half *xnh, *ynh0, *ynh1, *finwh, *binwh, *pwh, *fTh, *bTh, *wcath, *xbc0h, *xbc1h;
    float *zx0, *zx1, *dtg, *dAg, *ysp;
    cudaGetSymbolAddress((void**)&xnh, g_xnh);
    cudaGetSymbolAddress((void**)&zx0, g_zx0);
    cudaGetSymbolAddress((void**)&zx1, g_zx1);
    cudaGetSymbolAddress((void**)&xbc0h, g_xbc0h);
    cudaGetSymbolAddress((void**)&xbc1h, g_xbc1h);
    cudaGetSymbolAddress((void**)&dtg, g_dt);
    cudaGetSymbolAddress((void**)&dAg, g_dA);
    cudaGetSymbolAddress((void**)&ysp, g_ysp);
    cudaGetSymbolAddress((void**)&ynh0, g_ynh0);
    cudaGetSymbolAddress((void**)&ynh1, g_ynh1);
    cudaGetSymbolAddress((void**)&finwh, g_finwh);
    cudaGetSymbolAddress((void**)&binwh, g_binwh);
    cudaGetSymbolAddress((void**)&pwh, g_pwh);
    cudaGetSymbolAddress((void**)&fTh, g_fTh);
    cudaGetSymbolAddress((void**)&bTh, g_bTh);
    cudaGetSymbolAddress((void**)&wcath, g_wcath);

    const int SM128 = 3 * (128 + 128) * 40 * 2;
    const int SM64  = 3 * (64 + 128) * 40 * 2;
    cudaFuncSetAttribute(gemm_h<128>, cudaFuncAttributeMaxDynamicSharedMemorySize, SM128);
    cudaFuncSetAttribute(gemm_h<64>,  cudaFuncAttributeMaxDynamicSharedMemorySize, SM64);

    // 1: prep
    prep_kernel<<<PREP_BLKS, 256>>>(x, nw, xnh, f_in_w, finwh, b_in_w, binwh,
                                    pw, pwh, f_ow, fTh, b_ow, bTh);

    // 2: both in-projections
    gemm_h<128><<<dim3((DPROJ + 127) / 128, TT / 128, 2), 256, SM128>>>(
        xnh, nullptr, finwh, zx0, binwh, zx1, DPROJ, DM, DM, DPROJ, 0, 0, 0, nullptr, nullptr);

    // 3: fused conv + dt (conv output fp16)
    convdt_kernel<<<CONV_BLKS + DT_BLKS, 256>>>(zx0, zx1, f_cw, f_cb, b_cw, b_cb,
                                                xbc0h, xbc1h, f_dtb, f_Al, b_dtb, b_Al, dtg, dAg);

    // 4: scan (PROFILED SLOT) — 256 CTAs, split-4, fp16 inputs
    scan4h_kernel<<<256, 256>>>(xbc0h, xbc1h, dtg, dAg, f_D, b_D, ysp);

    // 5-6: tail weight combos
    gemm_h<128><<<dim3(DIN / 128, DM / 128), 256, SM128>>>(
        pwh, nullptr, fTh, wcath, nullptr, nullptr, DIN, DM, DIN, 2 * DIN, 0, 0, 1, nullptr, nullptr);
    gemm_h<128><<<dim3(DIN / 128, DM / 128), 256, SM128>>>(
        pwh, nullptr, bTh, wcath + DIN, nullptr, nullptr, DIN, DM, DIN, 2 * DIN, DM, 0, 1, nullptr, nullptr);

    // 7: gating + inner rmsnorm
    gate_norm_kernel<<<2 * TT, 256>>>(ysp, zx0, zx1, f_nw, b_nw, ynh0, ynh1);

    // 8: fused tail GEMM
    gemm_h<64><<<dim3(DM / 128, TT / 64), 256, SM64>>>(
        ynh0, ynh1, wcath, d_out, nullptr, nullptr, DM, 2 * DIN, DIN, DM, 0, 2, 0, pb, x);
}